// round 11
// baseline (speedup 1.0000x reference)
#include <cuda_runtime.h>
#include <cuda_fp16.h>
#include <cstdint>

#define NSTATE 1024
#define NHEAD  16
#define HDIM   64
#define TMAX   6144

// Scratch (device globals: allocation-free rule). All activations in fp16.
__device__ __half g_qh[TMAX * NSTATE];     // pre-scaled by QSCALE
__device__ __half g_kh[TMAX * NSTATE];
__device__ __half g_vh[TMAX * NSTATE];
__device__ __half g_ctxh[TMAX * NSTATE];
__device__ __half g_xh[TMAX * NSTATE];
__device__ __half g_wqh[NSTATE * NSTATE];
__device__ __half g_wkh[NSTATE * NSTATE];
__device__ __half g_wvh[NSTATE * NSTATE];
__device__ __half g_woh[NSTATE * NSTATE];

#define QSCALE (0.125f * 1.44269504088896340736f)   // 1/sqrt(64) * log2(e)

// FMA-only exp2 for y <= 0 (softmax path). |rel err| ~ 2e-6.
__device__ __forceinline__ float exp2f_fast(float y) {
    y = fmaxf(y, -100.f);
    float z = __fadd_rn(y, 12582912.f);
    float r = __fsub_rn(z, 12582912.f);
    float f = y - r;
    int   n = __float_as_int(z) - 0x4B400000;
    float p = 1.3333558e-3f;
    p = fmaf(p, f, 9.6181291e-3f);
    p = fmaf(p, f, 5.5504109e-2f);
    p = fmaf(p, f, 2.4022651e-1f);
    p = fmaf(p, f, 6.9314718e-1f);
    p = fmaf(p, f, 1.0f);
    return __int_as_float(__float_as_int(p) + (n << 23));
}

__device__ __forceinline__ unsigned h2u(__half2 h) {
    return *reinterpret_cast<unsigned*>(&h);
}

__device__ __forceinline__ void ldsm4(unsigned& r0, unsigned& r1,
                                      unsigned& r2, unsigned& r3, uint32_t a) {
    asm volatile("ldmatrix.sync.aligned.m8n8.x4.shared.b16 {%0,%1,%2,%3}, [%4];"
                 : "=r"(r0), "=r"(r1), "=r"(r2), "=r"(r3) : "r"(a));
}
__device__ __forceinline__ void ldsm4t(unsigned& r0, unsigned& r1,
                                       unsigned& r2, unsigned& r3, uint32_t a) {
    asm volatile("ldmatrix.sync.aligned.m8n8.x4.trans.shared.b16 {%0,%1,%2,%3}, [%4];"
                 : "=r"(r0), "=r"(r1), "=r"(r2), "=r"(r3) : "r"(a));
}
#define MMA16816(d0,d1,d2,d3,a0,a1,a2,a3,b0,b1)                            \
    asm volatile(                                                          \
        "mma.sync.aligned.m16n8k16.row.col.f32.f16.f16.f32 "               \
        "{%0,%1,%2,%3}, {%4,%5,%6,%7}, {%8,%9}, {%0,%1,%2,%3};\n"          \
        : "+f"(d0), "+f"(d1), "+f"(d2), "+f"(d3)                           \
        : "r"(a0), "r"(a1), "r"(a2), "r"(a3), "r"(b0), "r"(b1))

__device__ __forceinline__ void cp16(uint32_t dst, const void* src) {
    asm volatile("cp.async.cg.shared.global [%0], [%1], 16;\n"
                 :: "r"(dst), "l"(src));
}
// cp.async with src-size: zero-fills when sz==0
__device__ __forceinline__ void cp16z(uint32_t dst, const void* src, int sz) {
    asm volatile("cp.async.cg.shared.global [%0], [%1], 16, %2;\n"
                 :: "r"(dst), "l"(src), "r"(sz));
}

// ---------------------------------------------------------------------------
// Fused fp32 -> fp16 conversion of x + 4 weight matrices. One launch.
// ---------------------------------------------------------------------------
__global__ __launch_bounds__(256)
void cvt_h_kernel(const float* __restrict__ x,
                  const float* __restrict__ wq, const float* __restrict__ wk,
                  const float* __restrict__ wv, const float* __restrict__ wo)
{
    const int bid = blockIdx.x;
    const float* s; __half* d;
    if (bid < TMAX) {
        s = x + (size_t)bid * NSTATE;
        d = g_xh + (size_t)bid * NSTATE;
    } else {
        const int r = bid - TMAX;
        const int w = r >> 10, row = r & 1023;
        const float* ws = (w == 0) ? wq : (w == 1) ? wk : (w == 2) ? wv : wo;
        __half* ds = (w == 0) ? g_wqh : (w == 1) ? g_wkh : (w == 2) ? g_wvh : g_woh;
        s = ws + (size_t)row * NSTATE;
        d = ds + (size_t)row * NSTATE;
    }
    const int i = threadIdx.x * 4;
    float4 v = *(const float4*)(s + i);
    __half2 h0 = __floats2half2_rn(v.x, v.y);
    __half2 h1 = __floats2half2_rn(v.z, v.w);
    uint2 u; u.x = h2u(h0); u.y = h2u(h1);
    *(uint2*)(d + i) = u;
}

// ---------------------------------------------------------------------------
// fp16 tensor-core GEMM NT: C[M,N] = A[M,K] @ W[N,K]^T (+bias) * scale
// CTA 128x64, BK=64, 8 warps (4x2), warp tile 32x32 (acc 32 regs),
// 2-stage cp.async, ldmatrix.x4, launch_bounds(256,3) -> 3 CTAs/SM.
// ---------------------------------------------------------------------------
#define HSTR 72                  // halves per smem row (144 B, conflict-free)
#define HBUFA (128 * HSTR)       // A tile halves
#define HBUFW (64 * HSTR)        // W tile halves
#define HBUFA_B (HBUFA * 2)      // 18432 B
#define STAGE_B ((HBUFA + HBUFW) * 2)   // 27648 B per stage
#define GEMM_SMEM (2 * STAGE_B)  // 55296 B
#define NCH (NSTATE / 64)        // 16 k-chunks

template<bool OUTH>
__device__ __forceinline__ void gemm_h_body(const __half* __restrict__ A,
                                            const __half* __restrict__ W,
                                            const float* __restrict__ bias,
                                            void* __restrict__ Cv, float scale)
{
    extern __shared__ __half smh[];

    const int tid = threadIdx.x, lane = tid & 31, warp = tid >> 5;
    const int g = lane >> 2, tg = lane & 3;
    const int wm = (warp >> 1) * 32;          // 4 warp rows
    const int wn = (warp & 1) * 32;           // 2 warp cols
    const int bm = blockIdx.y * 128, bn = blockIdx.x * 64;
    const uint32_t sbase = (uint32_t)__cvta_generic_to_shared(smh);

    const int sel = lane >> 3;
    const int a_r = (lane & 7) + (sel & 1) * 8;
    const int a_c = (sel >> 1) * 8;
    const int b_r = (lane & 7) + (sel >> 1) * 8;
    const int b_c = (sel & 1) * 8;

    float acc[2][4][4];
#pragma unroll
    for (int a = 0; a < 2; a++)
#pragma unroll
        for (int b = 0; b < 4; b++)
#pragma unroll
            for (int c = 0; c < 4; c++) acc[a][b][c] = 0.f;

    // fill one stage: A 128 rows + W 64 rows, 64 halves each
    auto fill = [&](int stage, int kt) {
        const uint32_t off = sbase + (uint32_t)stage * STAGE_B;
#pragma unroll
        for (int i = 0; i < 4; i++) {
            const int idx = tid + i * 256;
            const int row = idx >> 3, seg = idx & 7;
            cp16(off + (uint32_t)(row * HSTR + seg * 8) * 2u,
                 A + (size_t)(bm + row) * NSTATE + kt + seg * 8);
        }
#pragma unroll
        for (int i = 0; i < 2; i++) {
            const int idx = tid + i * 256;
            const int row = idx >> 3, seg = idx & 7;
            cp16(off + HBUFA_B + (uint32_t)(row * HSTR + seg * 8) * 2u,
                 W + (size_t)(bn + row) * NSTATE + kt + seg * 8);
        }
        asm volatile("cp.async.commit_group;\n");
    };

    fill(0, 0);

    for (int t = 0; t < NCH; t++) {
        asm volatile("cp.async.wait_group 0;\n" ::: "memory");
        __syncthreads();                       // stage t ready; stage t-1 reads done

        if (t + 1 < NCH) fill((t + 1) & 1, (t + 1) * 64);   // safe: after barrier

        const uint32_t sb = sbase + (uint32_t)(t & 1) * STAGE_B;

#pragma unroll
        for (int ks = 0; ks < 4; ks++) {
            unsigned af[2][4], bf[4][2];
#pragma unroll
            for (int mt = 0; mt < 2; mt++)
                ldsm4(af[mt][0], af[mt][1], af[mt][2], af[mt][3],
                      sb + (uint32_t)((wm + mt * 16 + a_r) * HSTR + ks * 16 + a_c) * 2u);
#pragma unroll
            for (int np = 0; np < 2; np++)
                ldsm4(bf[2 * np][0], bf[2 * np][1], bf[2 * np + 1][0], bf[2 * np + 1][1],
                      sb + HBUFA_B +
                      (uint32_t)((wn + np * 16 + b_r) * HSTR + ks * 16 + b_c) * 2u);
#pragma unroll
            for (int mt = 0; mt < 2; mt++)
#pragma unroll
                for (int nt = 0; nt < 4; nt++)
                    MMA16816(acc[mt][nt][0], acc[mt][nt][1],
                             acc[mt][nt][2], acc[mt][nt][3],
                             af[mt][0], af[mt][1], af[mt][2], af[mt][3],
                             bf[nt][0], bf[nt][1]);
        }
    }

#pragma unroll
    for (int nt = 0; nt < 4; nt++) {
        const int col = bn + wn + nt * 8 + 2 * tg;
        float b0 = 0.f, b1 = 0.f;
        if (bias) { b0 = bias[col]; b1 = bias[col + 1]; }
#pragma unroll
        for (int mt = 0; mt < 2; mt++) {
            const int row = bm + wm + mt * 16 + g;
            const float v0 = (acc[mt][nt][0] + b0) * scale;
            const float v1 = (acc[mt][nt][1] + b1) * scale;
            const float v2 = (acc[mt][nt][2] + b0) * scale;
            const float v3 = (acc[mt][nt][3] + b1) * scale;
            if (OUTH) {
                __half* Ch = (__half*)Cv;
                *(__half2*)&Ch[(size_t)row * NSTATE + col]       = __floats2half2_rn(v0, v1);
                *(__half2*)&Ch[(size_t)(row + 8) * NSTATE + col] = __floats2half2_rn(v2, v3);
            } else {
                float* Cf = (float*)Cv;
                *(float2*)&Cf[(size_t)row * NSTATE + col]       = make_float2(v0, v1);
                *(float2*)&Cf[(size_t)(row + 8) * NSTATE + col] = make_float2(v2, v3);
            }
        }
    }
}

__global__ __launch_bounds__(256, 3)
void qkv_h_kernel(const float* __restrict__ bq, const float* __restrict__ bv)
{
    if (blockIdx.z == 0)
        gemm_h_body<true>(g_xh, g_wqh, bq,      g_qh, QSCALE);
    else if (blockIdx.z == 1)
        gemm_h_body<true>(g_xh, g_wkh, nullptr, g_kh, 1.f);
    else
        gemm_h_body<true>(g_xh, g_wvh, bv,      g_vh, 1.f);
}

__global__ __launch_bounds__(256, 3)
void oproj_h_kernel(const float* __restrict__ bo, float* __restrict__ out)
{
    gemm_h_body<false>(g_ctxh, g_woh, bo, out, 1.f);
}

// ---------------------------------------------------------------------------
// Flash attention, fp16 m16n8k16 + FMA exp2 (log2 domain), FA2 register P,
// cp.async double-buffered K/V tiles.  (R8 config: 64-query tiles, 128 thr)
// ---------------------------------------------------------------------------
#define ATS 72
#define AT32 (ATS / 2)

__global__ __launch_bounds__(128)
void attn_h_kernel(const int* __restrict__ cu, int nseq)
{
    __shared__ __half Qs[64 * ATS];
    __shared__ __half Kd[2][64 * ATS];
    __shared__ __half Vd[2][64 * ATS];

    const int h = blockIdx.y;

    int s0 = 0, L = 0, q0 = 0, found = 0;
    {
        int acct = 0;
        const int gt = blockIdx.x;
        for (int b = 0; b < nseq; b++) {
            const int s = cu[b], e = cu[b + 1];
            const int Lb = e - s;
            const int nt = (Lb + 63) >> 6;
            if (gt < acct + nt) { s0 = s; L = Lb; q0 = s + (gt - acct) * 64; found = 1; break; }
            acct += nt;
        }
    }
    if (!found) return;

    const int tid = threadIdx.x, lane = tid & 31, warp = tid >> 5;
    const int g = lane >> 2, tg = lane & 3;
    const int qrow0 = warp * 16;
    const int qrows = min(64, s0 + L - q0);

    const int sel = lane >> 3;
    const int kb_r = (lane & 7) + (sel >> 1) * 8;   // K (non-trans)
    const int kb_c = (sel & 1) * 8;
    const int vb_r = (lane & 7) + (sel & 1) * 8;    // V (trans)
    const int vb_c = (sel >> 1) * 8;

    auto load_kv = [&](int buf, int kt) {
        const int kbase = kt * 64;
        const int kc = min(64, L - kbase);
        const uint32_t kdst = (uint32_t)__cvta_generic_to_shared(Kd[buf]);
        const uint32_t vdst = (uint32_t)__cvta_generic_to_shared(Vd[buf]);
#pragma unroll
        for (int it = 0; it < 4; it++) {
            const int idx = tid + it * 128;
            const int r = idx >> 3, c8 = (idx & 7) * 8;
            const int ok = (r < kc) ? 16 : 0;
            const int rr = (r < kc) ? r : 0;
            const size_t go = (size_t)(s0 + kbase + rr) * NSTATE + h * HDIM + c8;
            const uint32_t so = (uint32_t)(r * ATS + c8) * 2u;
            cp16z(kdst + so, &g_kh[go], ok);
            cp16z(vdst + so, &g_vh[go], ok);
        }
        asm volatile("cp.async.commit_group;\n");
    };

    // Q fill (g_qh is pre-scaled by QSCALE)
#pragma unroll
    for (int it = 0; it < 4; it++) {
        const int idx = tid + it * 128;
        const int r = idx >> 3, c8 = (idx & 7) * 8;
        int4 v = make_int4(0, 0, 0, 0);
        if (r < qrows)
            v = *(const int4*)&g_qh[(size_t)(q0 + r) * NSTATE + h * HDIM + c8];
        *(int4*)&Qs[r * ATS + c8] = v;
    }

    const int nkt = (L + 63) >> 6;
    load_kv(0, 0);
    __syncthreads();

    const uint32_t* Q32 = (const uint32_t*)Qs;
    unsigned qf[4][4];
#pragma unroll
    for (int ks = 0; ks < 4; ks++) {
        const int base = (qrow0 + g) * AT32 + ks * 8 + tg;
        qf[ks][0] = Q32[base];
        qf[ks][1] = Q32[base + 8 * AT32];
        qf[ks][2] = Q32[base + 4];
        qf[ks][3] = Q32[base + 8 * AT32 + 4];
    }

    float m0 = -1e30f, m1 = -1e30f, l0 = 0.f, l1 = 0.f;
    float o[8][4];
#pragma unroll
    for (int nt = 0; nt < 8; nt++)
#pragma unroll
        for (int j = 0; j < 4; j++) o[nt][j] = 0.f;

    for (int kt = 0; kt < nkt; kt++) {
        const int b = kt & 1;
        const int kc = min(64, L - kt * 64);

        asm volatile("cp.async.wait_group 0;\n" ::: "memory");
        __syncthreads();

        if (kt + 1 < nkt) load_kv(1 - b, kt + 1);

        const uint32_t ksb = (uint32_t)__cvta_generic_to_shared(Kd[b]);
        const uint32_t vsb = (uint32_t)__cvta_generic_to_shared(Vd[b]);

        float s[8][4];
#pragma unroll
        for (int nt = 0; nt < 8; nt++)
#pragma unroll
            for (int j = 0; j < 4; j++) s[nt][j] = 0.f;

#pragma unroll
        for (int ks = 0; ks < 4; ks++) {
            unsigned bk[8][2];
#pragma unroll
            for (int np = 0; np < 4; np++)
                ldsm4(bk[2 * np][0], bk[2 * np][1],
                      bk[2 * np + 1][0], bk[2 * np + 1][1],
                      ksb + (uint32_t)((np * 16 + kb_r) * ATS + ks * 16 + kb_c) * 2u);
#pragma unroll
            for (int nt = 0; nt < 8; nt++)
                MMA16816(s[nt][0], s[nt][1], s[nt][2], s[nt][3],
                         qf[ks][0], qf[ks][1], qf[ks][2], qf[ks][3],
                         bk[nt][0], bk[nt][1]);
        }

        if (kc < 64) {
#pragma unroll
            for (int nt = 0; nt < 8; nt++) {
                const int c = nt * 8 + 2 * tg;
                if (c >= kc)     { s[nt][0] = -1e30f; s[nt][2] = -1e30f; }
                if (c + 1 >= kc) { s[nt][1] = -1e30f; s[nt][3] = -1e30f; }
            }
        }

        float mt0 = -1e30f, mt1 = -1e30f;
#pragma unroll
        for (int nt = 0; nt < 8; nt++) {
            mt0 = fmaxf(mt0, fmaxf(s[nt][0], s[nt][1]));
            mt1 = fmaxf(mt1, fmaxf(s[nt][2], s[nt][3]));
        }
        mt0 = fmaxf(mt0, __shfl_xor_sync(0xffffffffu, mt0, 1));
        mt0 = fmaxf(mt0, __shfl_xor_sync(0xffffffffu, mt0, 2));
        mt1 = fmaxf(mt1, __shfl_xor_sync(0xffffffffu, mt1, 1));
        mt1 = fmaxf(mt1, __shfl_xor_sync(0xffffffffu, mt1, 2));

        const float mn0 = fmaxf(m0, mt0), mn1 = fmaxf(m1, mt1);
        const float a0 = exp2f_fast(m0 - mn0), a1 = exp2f_fast(m1 - mn1);

        unsigned ph0[8], ph1[8];
        float r0 = 0.f, r1 = 0.f;
#pragma unroll
        for (int nt = 0; nt < 8; nt++) {
            const float e0 = exp2f_fast(s[nt][0] - mn0);
            const float e1 = exp2f_fast(s[nt][1] - mn0);
            const float e2 = exp2f_fast(s[nt][2] - mn1);
            const float e3 = exp2f_fast(s[nt][3] - mn1);
            __half2 hA = __floats2half2_rn(e0, e1);
            __half2 hB = __floats2half2_rn(e2, e3);
            float2 fA = __half22float2(hA);
            float2 fB = __half22float2(hB);
            r0 += fA.x + fA.y;
            r1 += fB.x + fB.y;
            ph0[nt] = h2u(hA);
            ph1[nt] = h2u(hB);
        }
        r0 += __shfl_xor_sync(0xffffffffu, r0, 1);
        r0 += __shfl_xor_sync(0xffffffffu, r0, 2);
        r1 += __shfl_xor_sync(0xffffffffu, r1, 1);
        r1 += __shfl_xor_sync(0xffffffffu, r1, 2);
        l0 = l0 * a0 + r0; l1 = l1 * a1 + r1;
        m0 = mn0; m1 = mn1;
#pragma unroll
        for (int nt = 0; nt < 8; nt++) {
            o[nt][0] *= a0; o[nt][1] *= a0;
            o[nt][2] *= a1; o[nt][3] *= a1;
        }

#pragma unroll
        for (int ks = 0; ks < 4; ks++) {
            const unsigned pa0 = ph0[2 * ks],     pa1 = ph1[2 * ks];
            const unsigned pa2 = ph0[2 * ks + 1], pa3 = ph1[2 * ks + 1];
            unsigned bv[8][2];
#pragma unroll
            for (int np = 0; np < 4; np++)
                ldsm4t(bv[2 * np][0], bv[2 * np][1],
                       bv[2 * np + 1][0], bv[2 * np + 1][1],
                       vsb + (uint32_t)((ks * 16 + vb_r) * ATS + np * 16 + vb_c) * 2u);
#pragma unroll
            for (int nt = 0; nt < 8; nt++)
                MMA16816(o[nt][0], o[nt][1], o[nt][2], o[nt][3],
                         pa0, pa1, pa2, pa3, bv[nt][0], bv[nt][1]);
        }
    }

    const float il0 = 1.f / l0, il1 = 1.f / l1;
    const int r0g = qrow0 + g, r1g = r0g + 8;
#pragma unroll
    for (int nt = 0; nt < 8; nt++) {
        const int c = nt * 8 + 2 * tg;
        if (r0g < qrows) {
            __half2 w = __floats2half2_rn(o[nt][0] * il0, o[nt][1] * il0);
            *(__half2*)&g_ctxh[(size_t)(q0 + r0g) * NSTATE + h * HDIM + c] = w;
        }
        if (r1g < qrows) {
            __half2 w = __floats2half2_rn(o[nt][2] * il1, o[nt][3] * il1);
            *(__half2*)&g_ctxh[(size_t)(q0 + r1g) * NSTATE + h * HDIM + c] = w;
        }
    }
}

// ---------------------------------------------------------------------------
// Launch. Inputs: 0=x, 1=cu_seqlens, 2=Wq, 3=bq, 4=Wk, 5=Wv, 6=bv, 7=Wo, 8=bo
// ---------------------------------------------------------------------------
extern "C" void kernel_launch(void* const* d_in, const int* in_sizes, int n_in,
                              void* d_out, int out_size)
{
    const float* x  = (const float*)d_in[0];
    const int*   cu = (const int*)d_in[1];
    const float* Wq = (const float*)d_in[2];
    const float* bq = (const float*)d_in[3];
    const float* Wk = (const float*)d_in[4];
    const float* Wv = (const float*)d_in[5];
    const float* bv = (const float*)d_in[6];
    const float* Wo = (const float*)d_in[7];
    const float* bo = (const float*)d_in[8];

    const int T = in_sizes[0] / NSTATE;       // 6144
    const int nseq = in_sizes[1] - 1;         // 8

    cudaFuncSetAttribute(qkv_h_kernel,
                         cudaFuncAttributeMaxDynamicSharedMemorySize, GEMM_SMEM);
    cudaFuncSetAttribute(oproj_h_kernel,
                         cudaFuncAttributeMaxDynamicSharedMemorySize, GEMM_SMEM);

    cvt_h_kernel<<<TMAX + 4 * NSTATE, 256>>>(x, Wq, Wk, Wv, Wo);

    dim3 gqkv(NSTATE / 64, T / 128, 3);       // 16 x 48 x 3
    qkv_h_kernel<<<gqkv, 256, GEMM_SMEM>>>(bq, bv);

    const int maxTiles = T / 64 + nseq;
    dim3 gattn(maxTiles, NHEAD);
    attn_h_kernel<<<gattn, 128>>>(cu, nseq);

    dim3 go(NSTATE / 64, T / 128);            // 16 x 48
    oproj_h_kernel<<<go, 256, GEMM_SMEM>>>(bo, (float*)d_out);
}

// round 12
// speedup vs baseline: 1.1095x; 1.1095x over previous
#include <cuda_runtime.h>
#include <cuda_fp16.h>
#include <cstdint>

#define NSTATE 1024
#define NHEAD  16
#define HDIM   64
#define TMAX   6144

// Scratch (device globals: allocation-free rule). All activations in fp16.
__device__ __half g_qh[TMAX * NSTATE];     // pre-scaled by QSCALE
__device__ __half g_kh[TMAX * NSTATE];
__device__ __half g_vh[TMAX * NSTATE];
__device__ __half g_ctxh[TMAX * NSTATE];
__device__ __half g_xh[TMAX * NSTATE];
__device__ __half g_wqh[NSTATE * NSTATE];
__device__ __half g_wkh[NSTATE * NSTATE];
__device__ __half g_wvh[NSTATE * NSTATE];
__device__ __half g_woh[NSTATE * NSTATE];

#define QSCALE (0.125f * 1.44269504088896340736f)   // 1/sqrt(64) * log2(e)

// MUFU exp2 (log2-domain softmax). Very negative input underflows to 0.
__device__ __forceinline__ float ex2f(float x) {
    float y; asm("ex2.approx.f32 %0, %1;" : "=f"(y) : "f"(x)); return y;
}

__device__ __forceinline__ unsigned h2u(__half2 h) {
    return *reinterpret_cast<unsigned*>(&h);
}

__device__ __forceinline__ void ldsm4(unsigned& r0, unsigned& r1,
                                      unsigned& r2, unsigned& r3, uint32_t a) {
    asm volatile("ldmatrix.sync.aligned.m8n8.x4.shared.b16 {%0,%1,%2,%3}, [%4];"
                 : "=r"(r0), "=r"(r1), "=r"(r2), "=r"(r3) : "r"(a));
}
__device__ __forceinline__ void ldsm4t(unsigned& r0, unsigned& r1,
                                       unsigned& r2, unsigned& r3, uint32_t a) {
    asm volatile("ldmatrix.sync.aligned.m8n8.x4.trans.shared.b16 {%0,%1,%2,%3}, [%4];"
                 : "=r"(r0), "=r"(r1), "=r"(r2), "=r"(r3) : "r"(a));
}
#define MMA16816(d0,d1,d2,d3,a0,a1,a2,a3,b0,b1)                            \
    asm volatile(                                                          \
        "mma.sync.aligned.m16n8k16.row.col.f32.f16.f16.f32 "               \
        "{%0,%1,%2,%3}, {%4,%5,%6,%7}, {%8,%9}, {%0,%1,%2,%3};\n"          \
        : "+f"(d0), "+f"(d1), "+f"(d2), "+f"(d3)                           \
        : "r"(a0), "r"(a1), "r"(a2), "r"(a3), "r"(b0), "r"(b1))

__device__ __forceinline__ void cp16(uint32_t dst, const void* src) {
    asm volatile("cp.async.cg.shared.global [%0], [%1], 16;\n"
                 :: "r"(dst), "l"(src));
}
// cp.async with src-size: zero-fills when sz==0
__device__ __forceinline__ void cp16z(uint32_t dst, const void* src, int sz) {
    asm volatile("cp.async.cg.shared.global [%0], [%1], 16, %2;\n"
                 :: "r"(dst), "l"(src), "r"(sz));
}

// ---------------------------------------------------------------------------
// Fused fp32 -> fp16 conversion of x + 4 weight matrices. One launch.
// ---------------------------------------------------------------------------
__global__ __launch_bounds__(256)
void cvt_h_kernel(const float* __restrict__ x,
                  const float* __restrict__ wq, const float* __restrict__ wk,
                  const float* __restrict__ wv, const float* __restrict__ wo)
{
    const int bid = blockIdx.x;
    const float* s; __half* d;
    if (bid < TMAX) {
        s = x + (size_t)bid * NSTATE;
        d = g_xh + (size_t)bid * NSTATE;
    } else {
        const int r = bid - TMAX;
        const int w = r >> 10, row = r & 1023;
        const float* ws = (w == 0) ? wq : (w == 1) ? wk : (w == 2) ? wv : wo;
        __half* ds = (w == 0) ? g_wqh : (w == 1) ? g_wkh : (w == 2) ? g_wvh : g_woh;
        s = ws + (size_t)row * NSTATE;
        d = ds + (size_t)row * NSTATE;
    }
    const int i = threadIdx.x * 4;
    float4 v = *(const float4*)(s + i);
    __half2 h0 = __floats2half2_rn(v.x, v.y);
    __half2 h1 = __floats2half2_rn(v.z, v.w);
    uint2 u; u.x = h2u(h0); u.y = h2u(h1);
    *(uint2*)(d + i) = u;
}

// ---------------------------------------------------------------------------
// fp16 tensor-core GEMM NT: C[M,N] = A[M,K] @ W[N,K]^T (+bias) * scale
// CTA 128x128, BK=64, 8 warps (2x4), warp 64x32, mma m16n8k16,
// 3-stage cp.async pipeline, ldmatrix.x4.  (exact round-8 configuration)
// ---------------------------------------------------------------------------
#define HSTR 72                  // halves per smem row (144 B, conflict-free)
#define HBUF (128 * HSTR)        // halves per tile
#define HBUF_B (HBUF * 2)        // bytes per tile (18432)
#define GEMM_SMEM (3 * 2 * HBUF_B)   // 110592 B (3 stages x [A,W])
#define NCH (NSTATE / 64)        // 16 k-chunks

template<bool OUTH>
__device__ __forceinline__ void gemm_h_body(const __half* __restrict__ A,
                                            const __half* __restrict__ W,
                                            const float* __restrict__ bias,
                                            void* __restrict__ Cv, float scale)
{
    extern __shared__ __half smh[];

    const int tid = threadIdx.x, lane = tid & 31, warp = tid >> 5;
    const int g = lane >> 2, tg = lane & 3;
    const int wm = (warp >> 2) * 64, wn = (warp & 3) * 32;
    const int bm = blockIdx.y * 128, bn = blockIdx.x * 128;
    const uint32_t sbase = (uint32_t)__cvta_generic_to_shared(smh);

    const int sel = lane >> 3;
    const int a_r = (lane & 7) + (sel & 1) * 8;
    const int a_c = (sel >> 1) * 8;
    const int b_r = (lane & 7) + (sel >> 1) * 8;
    const int b_c = (sel & 1) * 8;

    float acc[4][4][4];
#pragma unroll
    for (int a = 0; a < 4; a++)
#pragma unroll
        for (int b = 0; b < 4; b++)
#pragma unroll
            for (int c = 0; c < 4; c++) acc[a][b][c] = 0.f;

    auto fill = [&](int stage, int kt) {
        const uint32_t off = sbase + (uint32_t)stage * (2u * HBUF_B);
#pragma unroll
        for (int i = 0; i < 4; i++) {
            const int idx = tid + i * 256;
            const int row = idx >> 3, seg = idx & 7;
            const uint32_t d = off + (uint32_t)(row * HSTR + seg * 8) * 2u;
            cp16(d,          A + (size_t)(bm + row) * NSTATE + kt + seg * 8);
            cp16(d + HBUF_B, W + (size_t)(bn + row) * NSTATE + kt + seg * 8);
        }
        asm volatile("cp.async.commit_group;\n");
    };

    fill(0, 0);
    fill(1, 64);

    for (int t = 0; t < NCH; t++) {
        if (t < NCH - 1) asm volatile("cp.async.wait_group 1;\n" ::: "memory");
        else             asm volatile("cp.async.wait_group 0;\n" ::: "memory");
        __syncthreads();

        if (t + 2 < NCH) fill((t + 2) % 3, (t + 2) * 64);

        const uint32_t sb = sbase + (uint32_t)(t % 3) * (2u * HBUF_B);

#pragma unroll
        for (int ks = 0; ks < 4; ks++) {
            unsigned af[4][4], bf[4][2];
#pragma unroll
            for (int mt = 0; mt < 4; mt++)
                ldsm4(af[mt][0], af[mt][1], af[mt][2], af[mt][3],
                      sb + (uint32_t)((wm + mt * 16 + a_r) * HSTR + ks * 16 + a_c) * 2u);
#pragma unroll
            for (int np = 0; np < 2; np++)
                ldsm4(bf[2 * np][0], bf[2 * np][1], bf[2 * np + 1][0], bf[2 * np + 1][1],
                      sb + HBUF_B +
                      (uint32_t)((wn + np * 16 + b_r) * HSTR + ks * 16 + b_c) * 2u);
#pragma unroll
            for (int mt = 0; mt < 4; mt++)
#pragma unroll
                for (int nt = 0; nt < 4; nt++)
                    MMA16816(acc[mt][nt][0], acc[mt][nt][1],
                             acc[mt][nt][2], acc[mt][nt][3],
                             af[mt][0], af[mt][1], af[mt][2], af[mt][3],
                             bf[nt][0], bf[nt][1]);
        }
    }

#pragma unroll
    for (int nt = 0; nt < 4; nt++) {
        const int col = bn + wn + nt * 8 + 2 * tg;
        float b0 = 0.f, b1 = 0.f;
        if (bias) { b0 = bias[col]; b1 = bias[col + 1]; }
#pragma unroll
        for (int mt = 0; mt < 4; mt++) {
            const int row = bm + wm + mt * 16 + g;
            const float v0 = (acc[mt][nt][0] + b0) * scale;
            const float v1 = (acc[mt][nt][1] + b1) * scale;
            const float v2 = (acc[mt][nt][2] + b0) * scale;
            const float v3 = (acc[mt][nt][3] + b1) * scale;
            if (OUTH) {
                __half* Ch = (__half*)Cv;
                *(__half2*)&Ch[(size_t)row * NSTATE + col]       = __floats2half2_rn(v0, v1);
                *(__half2*)&Ch[(size_t)(row + 8) * NSTATE + col] = __floats2half2_rn(v2, v3);
            } else {
                float* Cf = (float*)Cv;
                *(float2*)&Cf[(size_t)row * NSTATE + col]       = make_float2(v0, v1);
                *(float2*)&Cf[(size_t)(row + 8) * NSTATE + col] = make_float2(v2, v3);
            }
        }
    }
}

__global__ __launch_bounds__(256)
void qkv_h_kernel(const float* __restrict__ bq, const float* __restrict__ bv)
{
    if (blockIdx.z == 0)
        gemm_h_body<true>(g_xh, g_wqh, bq,      g_qh, QSCALE);
    else if (blockIdx.z == 1)
        gemm_h_body<true>(g_xh, g_wkh, nullptr, g_kh, 1.f);
    else
        gemm_h_body<true>(g_xh, g_wvh, bv,      g_vh, 1.f);
}

__global__ __launch_bounds__(256)
void oproj_h_kernel(const float* __restrict__ bo, float* __restrict__ out)
{
    gemm_h_body<false>(g_ctxh, g_woh, bo, out, 1.f);
}

// ---------------------------------------------------------------------------
// Flash attention, fp16 m16n8k16, FA2 register P, cp.async double-buffered
// K/V tiles (R8 config) + MUFU ex2 softmax (log2 domain, scale in Q).
// CTA: 64 queries x 1 head, 4 warps x 16 rows. smem stride 72 halves.
// ---------------------------------------------------------------------------
#define ATS 72
#define AT32 (ATS / 2)

__global__ __launch_bounds__(128)
void attn_h_kernel(const int* __restrict__ cu, int nseq)
{
    __shared__ __half Qs[64 * ATS];
    __shared__ __half Kd[2][64 * ATS];
    __shared__ __half Vd[2][64 * ATS];

    const int h = blockIdx.y;

    int s0 = 0, L = 0, q0 = 0, found = 0;
    {
        int acct = 0;
        const int gt = blockIdx.x;
        for (int b = 0; b < nseq; b++) {
            const int s = cu[b], e = cu[b + 1];
            const int Lb = e - s;
            const int nt = (Lb + 63) >> 6;
            if (gt < acct + nt) { s0 = s; L = Lb; q0 = s + (gt - acct) * 64; found = 1; break; }
            acct += nt;
        }
    }
    if (!found) return;

    const int tid = threadIdx.x, lane = tid & 31, warp = tid >> 5;
    const int g = lane >> 2, tg = lane & 3;
    const int qrow0 = warp * 16;
    const int qrows = min(64, s0 + L - q0);

    const int sel = lane >> 3;
    const int kb_r = (lane & 7) + (sel >> 1) * 8;   // K (non-trans)
    const int kb_c = (sel & 1) * 8;
    const int vb_r = (lane & 7) + (sel & 1) * 8;    // V (trans)
    const int vb_c = (sel >> 1) * 8;

    auto load_kv = [&](int buf, int kt) {
        const int kbase = kt * 64;
        const int kc = min(64, L - kbase);
        const uint32_t kdst = (uint32_t)__cvta_generic_to_shared(Kd[buf]);
        const uint32_t vdst = (uint32_t)__cvta_generic_to_shared(Vd[buf]);
#pragma unroll
        for (int it = 0; it < 4; it++) {
            const int idx = tid + it * 128;
            const int r = idx >> 3, c8 = (idx & 7) * 8;
            const int ok = (r < kc) ? 16 : 0;
            const int rr = (r < kc) ? r : 0;
            const size_t go = (size_t)(s0 + kbase + rr) * NSTATE + h * HDIM + c8;
            const uint32_t so = (uint32_t)(r * ATS + c8) * 2u;
            cp16z(kdst + so, &g_kh[go], ok);
            cp16z(vdst + so, &g_vh[go], ok);
        }
        asm volatile("cp.async.commit_group;\n");
    };

    // Q fill (g_qh is pre-scaled by QSCALE)
#pragma unroll
    for (int it = 0; it < 4; it++) {
        const int idx = tid + it * 128;
        const int r = idx >> 3, c8 = (idx & 7) * 8;
        int4 v = make_int4(0, 0, 0, 0);
        if (r < qrows)
            v = *(const int4*)&g_qh[(size_t)(q0 + r) * NSTATE + h * HDIM + c8];
        *(int4*)&Qs[r * ATS + c8] = v;
    }

    const int nkt = (L + 63) >> 6;
    load_kv(0, 0);
    __syncthreads();

    const uint32_t* Q32 = (const uint32_t*)Qs;
    unsigned qf[4][4];
#pragma unroll
    for (int ks = 0; ks < 4; ks++) {
        const int base = (qrow0 + g) * AT32 + ks * 8 + tg;
        qf[ks][0] = Q32[base];
        qf[ks][1] = Q32[base + 8 * AT32];
        qf[ks][2] = Q32[base + 4];
        qf[ks][3] = Q32[base + 8 * AT32 + 4];
    }

    float m0 = -1e30f, m1 = -1e30f, l0 = 0.f, l1 = 0.f;
    float o[8][4];
#pragma unroll
    for (int nt = 0; nt < 8; nt++)
#pragma unroll
        for (int j = 0; j < 4; j++) o[nt][j] = 0.f;

    for (int kt = 0; kt < nkt; kt++) {
        const int b = kt & 1;
        const int kc = min(64, L - kt * 64);

        asm volatile("cp.async.wait_group 0;\n" ::: "memory");
        __syncthreads();

        if (kt + 1 < nkt) load_kv(1 - b, kt + 1);

        const uint32_t ksb = (uint32_t)__cvta_generic_to_shared(Kd[b]);
        const uint32_t vsb = (uint32_t)__cvta_generic_to_shared(Vd[b]);

        float s[8][4];
#pragma unroll
        for (int nt = 0; nt < 8; nt++)
#pragma unroll
            for (int j = 0; j < 4; j++) s[nt][j] = 0.f;

#pragma unroll
        for (int ks = 0; ks < 4; ks++) {
            unsigned bk[8][2];
#pragma unroll
            for (int np = 0; np < 4; np++)
                ldsm4(bk[2 * np][0], bk[2 * np][1],
                      bk[2 * np + 1][0], bk[2 * np + 1][1],
                      ksb + (uint32_t)((np * 16 + kb_r) * ATS + ks * 16 + kb_c) * 2u);
#pragma unroll
            for (int nt = 0; nt < 8; nt++)
                MMA16816(s[nt][0], s[nt][1], s[nt][2], s[nt][3],
                         qf[ks][0], qf[ks][1], qf[ks][2], qf[ks][3],
                         bk[nt][0], bk[nt][1]);
        }

        if (kc < 64) {
#pragma unroll
            for (int nt = 0; nt < 8; nt++) {
                const int c = nt * 8 + 2 * tg;
                if (c >= kc)     { s[nt][0] = -1e30f; s[nt][2] = -1e30f; }
                if (c + 1 >= kc) { s[nt][1] = -1e30f; s[nt][3] = -1e30f; }
            }
        }

        // online softmax (c0,c1 = row g; c2,c3 = row g+8), MUFU exp2
        float mt0 = -1e30f, mt1 = -1e30f;
#pragma unroll
        for (int nt = 0; nt < 8; nt++) {
            mt0 = fmaxf(mt0, fmaxf(s[nt][0], s[nt][1]));
            mt1 = fmaxf(mt1, fmaxf(s[nt][2], s[nt][3]));
        }
        mt0 = fmaxf(mt0, __shfl_xor_sync(0xffffffffu, mt0, 1));
        mt0 = fmaxf(mt0, __shfl_xor_sync(0xffffffffu, mt0, 2));
        mt1 = fmaxf(mt1, __shfl_xor_sync(0xffffffffu, mt1, 1));
        mt1 = fmaxf(mt1, __shfl_xor_sync(0xffffffffu, mt1, 2));

        const float mn0 = fmaxf(m0, mt0), mn1 = fmaxf(m1, mt1);
        const float a0 = ex2f(m0 - mn0), a1 = ex2f(m1 - mn1);

        unsigned ph0[8], ph1[8];
        float r0 = 0.f, r1 = 0.f;
#pragma unroll
        for (int nt = 0; nt < 8; nt++) {
            const float e0 = ex2f(s[nt][0] - mn0);
            const float e1 = ex2f(s[nt][1] - mn0);
            const float e2 = ex2f(s[nt][2] - mn1);
            const float e3 = ex2f(s[nt][3] - mn1);
            __half2 hA = __floats2half2_rn(e0, e1);
            __half2 hB = __floats2half2_rn(e2, e3);
            float2 fA = __half22float2(hA);
            float2 fB = __half22float2(hB);
            r0 += fA.x + fA.y;
            r1 += fB.x + fB.y;
            ph0[nt] = h2u(hA);
            ph1[nt] = h2u(hB);
        }
        r0 += __shfl_xor_sync(0xffffffffu, r0, 1);
        r0 += __shfl_xor_sync(0xffffffffu, r0, 2);
        r1 += __shfl_xor_sync(0xffffffffu, r1, 1);
        r1 += __shfl_xor_sync(0xffffffffu, r1, 2);
        l0 = l0 * a0 + r0; l1 = l1 * a1 + r1;
        m0 = mn0; m1 = mn1;
#pragma unroll
        for (int nt = 0; nt < 8; nt++) {
            o[nt][0] *= a0; o[nt][1] *= a0;
            o[nt][2] *= a1; o[nt][3] *= a1;
        }

        // O += P @ V  — P frags from S C-fragments; V frags via ldmatrix.trans
#pragma unroll
        for (int ks = 0; ks < 4; ks++) {
            const unsigned pa0 = ph0[2 * ks],     pa1 = ph1[2 * ks];
            const unsigned pa2 = ph0[2 * ks + 1], pa3 = ph1[2 * ks + 1];
            unsigned bv[8][2];
#pragma unroll
            for (int np = 0; np < 4; np++)
                ldsm4t(bv[2 * np][0], bv[2 * np][1],
                       bv[2 * np + 1][0], bv[2 * np + 1][1],
                       vsb + (uint32_t)((ks * 16 + vb_r) * ATS + np * 16 + vb_c) * 2u);
#pragma unroll
            for (int nt = 0; nt < 8; nt++)
                MMA16816(o[nt][0], o[nt][1], o[nt][2], o[nt][3],
                         pa0, pa1, pa2, pa3, bv[nt][0], bv[nt][1]);
        }
    }

    const float il0 = 1.f / l0, il1 = 1.f / l1;
    const int r0g = qrow0 + g, r1g = r0g + 8;
#pragma unroll
    for (int nt = 0; nt < 8; nt++) {
        const int c = nt * 8 + 2 * tg;
        if (r0g < qrows) {
            __half2 w = __floats2half2_rn(o[nt][0] * il0, o[nt][1] * il0);
            *(__half2*)&g_ctxh[(size_t)(q0 + r0g) * NSTATE + h * HDIM + c] = w;
        }
        if (r1g < qrows) {
            __half2 w = __floats2half2_rn(o[nt][2] * il1, o[nt][3] * il1);
            *(__half2*)&g_ctxh[(size_t)(q0 + r1g) * NSTATE + h * HDIM + c] = w;
        }
    }
}

// ---------------------------------------------------------------------------
// Launch. Inputs: 0=x, 1=cu_seqlens, 2=Wq, 3=bq, 4=Wk, 5=Wv, 6=bv, 7=Wo, 8=bo
// ---------------------------------------------------------------------------
extern "C" void kernel_launch(void* const* d_in, const int* in_sizes, int n_in,
                              void* d_out, int out_size)
{
    const float* x  = (const float*)d_in[0];
    const int*   cu = (const int*)d_in[1];
    const float* Wq = (const float*)d_in[2];
    const float* bq = (const float*)d_in[3];
    const float* Wk = (const float*)d_in[4];
    const float* Wv = (const float*)d_in[5];
    const float* bv = (const float*)d_in[6];
    const float* Wo = (const float*)d_in[7];
    const float* bo = (const float*)d_in[8];

    const int T = in_sizes[0] / NSTATE;       // 6144
    const int nseq = in_sizes[1] - 1;         // 8

    cudaFuncSetAttribute(qkv_h_kernel,
                         cudaFuncAttributeMaxDynamicSharedMemorySize, GEMM_SMEM);
    cudaFuncSetAttribute(oproj_h_kernel,
                         cudaFuncAttributeMaxDynamicSharedMemorySize, GEMM_SMEM);

    cvt_h_kernel<<<TMAX + 4 * NSTATE, 256>>>(x, Wq, Wk, Wv, Wo);

    dim3 gqkv(NSTATE / 128, T / 128, 3);
    qkv_h_kernel<<<gqkv, 256, GEMM_SMEM>>>(bq, bv);

    const int maxTiles = T / 64 + nseq;
    dim3 gattn(maxTiles, NHEAD);
    attn_h_kernel<<<gattn, 128>>>(cu, nseq);

    dim3 go(NSTATE / 128, T / 128);
    oproj_h_kernel<<<go, 256, GEMM_SMEM>>>(bo, (float*)d_out);
}